// round 1
// baseline (speedup 1.0000x reference)
#include <cuda_runtime.h>
#include <cuda_bf16.h>

#define R_TOTAL 32768   // 16384 b * 2 (values,mask)
#define NE      1024
#define H       128

// Scratch for projected values/mask: vm[2b+0]=values row, vm[2b+1]=mask row.
__device__ float g_vm[(size_t)R_TOTAL * H];

// ---------------------------------------------------------------------------
// Kernel 1: vm = X @ W^T     X:[32768,1024] (x flattened), W:[128,1024]
// Classic 128x128 block sgemm, BK=16, 256 threads, 8x8 per-thread tile.
// ---------------------------------------------------------------------------
__global__ __launch_bounds__(256) void gemm_vm(const float* __restrict__ X,
                                               const float* __restrict__ W) {
    __shared__ float As[16][129];
    __shared__ float Bs[16][132];

    const int tid  = threadIdx.x;
    const int row0 = blockIdx.x * 128;
    const int tx   = tid & 15;      // 0..15 -> 8 output cols each
    const int ty   = tid >> 4;      // 0..15 -> 8 output rows each

    const int lk = (tid & 3) * 4;   // k offset within 16-wide K tile
    const int lr = tid >> 2;        // 0..63 row/head within tile half

    float acc[8][8];
    #pragma unroll
    for (int j = 0; j < 8; ++j)
        #pragma unroll
        for (int i = 0; i < 8; ++i) acc[j][i] = 0.f;

    for (int k0 = 0; k0 < NE; k0 += 16) {
        // Load A tile (128 rows x 16 k), transposed into As[k][row]
        #pragma unroll
        for (int rr = 0; rr < 128; rr += 64) {
            float4 a = *reinterpret_cast<const float4*>(
                &X[(size_t)(row0 + lr + rr) * NE + k0 + lk]);
            As[lk + 0][lr + rr] = a.x;
            As[lk + 1][lr + rr] = a.y;
            As[lk + 2][lr + rr] = a.z;
            As[lk + 3][lr + rr] = a.w;
        }
        // Load B tile from W: Bs[k][h] = W[h, k0+k]   (128 h x 16 k)
        #pragma unroll
        for (int hh = 0; hh < 128; hh += 64) {
            float4 b = *reinterpret_cast<const float4*>(
                &W[(size_t)(lr + hh) * NE + k0 + lk]);
            Bs[lk + 0][lr + hh] = b.x;
            Bs[lk + 1][lr + hh] = b.y;
            Bs[lk + 2][lr + hh] = b.z;
            Bs[lk + 3][lr + hh] = b.w;
        }
        __syncthreads();

        #pragma unroll
        for (int k = 0; k < 16; ++k) {
            float a[8], b[8];
            #pragma unroll
            for (int j = 0; j < 8; ++j) a[j] = As[k][ty * 8 + j];
            #pragma unroll
            for (int i = 0; i < 8; ++i) b[i] = Bs[k][tx * 8 + i];
            #pragma unroll
            for (int j = 0; j < 8; ++j)
                #pragma unroll
                for (int i = 0; i < 8; ++i)
                    acc[j][i] = fmaf(a[j], b[i], acc[j][i]);
        }
        __syncthreads();
    }

    #pragma unroll
    for (int j = 0; j < 8; ++j) {
        float* dst = &g_vm[(size_t)(row0 + ty * 8 + j) * H + tx * 8];
        #pragma unroll
        for (int i = 0; i < 8; ++i) dst[i] = acc[j][i];
    }
}

// ---------------------------------------------------------------------------
// Kernel 2: per-b fused softmax head.
//   E[h][k] = exp(m[h] * cov[h][k]);  Z[h] = sum_k E;  w[h] = v[h]/Z[h]
//   out[b][k] = sum_h w[h]*E[h][k] + bias[k]
// One CTA (128 threads, thread = k) per b. E chunked 64 rows at a time in smem
// so every exp is computed exactly once. No max-subtraction needed: |m*cov|<~2.
// ---------------------------------------------------------------------------
__global__ __launch_bounds__(128) void head_out(const float* __restrict__ cov,
                                                const float* __restrict__ bias,
                                                float* __restrict__ out) {
    __shared__ float m_s[H], v_s[H], w_s[H];
    __shared__ float E[64][H + 1];

    const int b = blockIdx.x;
    const int k = threadIdx.x;

    v_s[k] = g_vm[(size_t)(2 * b + 0) * H + k];
    m_s[k] = g_vm[(size_t)(2 * b + 1) * H + k];
    __syncthreads();

    float acc = 0.f;

    #pragma unroll
    for (int hc = 0; hc < H; hc += 64) {
        // Fill: thread k computes column k for 64 h-rows
        #pragma unroll 4
        for (int h = 0; h < 64; ++h) {
            float c = __ldg(&cov[(size_t)(hc + h) * H + k]);
            E[h][k] = __expf(m_s[hc + h] * c);
        }
        __syncthreads();

        // Row sums (stride-129 rows -> conflict-free across threads)
        if (k < 64) {
            float Z = 0.f;
            #pragma unroll 8
            for (int j = 0; j < H; ++j) Z += E[k][j];
            w_s[hc + k] = v_s[hc + k] / Z;
        }
        __syncthreads();

        // Accumulate output column k over this h-chunk
        #pragma unroll 8
        for (int h = 0; h < 64; ++h)
            acc = fmaf(w_s[hc + h], E[h][k], acc);
        __syncthreads();   // protect E before next chunk's fill
    }

    out[(size_t)b * H + k] = acc + __ldg(&bias[k]);
}

// ---------------------------------------------------------------------------
extern "C" void kernel_launch(void* const* d_in, const int* in_sizes, int n_in,
                              void* d_out, int out_size) {
    const float* x    = (const float*)d_in[0];  // [16384,2,1024]
    const float* W    = (const float*)d_in[1];  // [128,1024]
    const float* cov  = (const float*)d_in[2];  // [128,128]
    const float* bias = (const float*)d_in[3];  // [128]
    float*       out  = (float*)d_out;          // [16384,128]

    gemm_vm<<<R_TOTAL / 128, 256>>>(x, W);
    head_out<<<16384, 128>>>(cov, bias, out);
}

// round 2
// speedup vs baseline: 1.5230x; 1.5230x over previous
#include <cuda_runtime.h>
#include <cuda_bf16.h>

#define R_TOTAL 32768   // 16384 b * 2 (values,mask)
#define NE      1024
#define H       128

// Scratch for projected values/mask: vm[2b+0]=values row, vm[2b+1]=mask row.
__device__ float g_vm[(size_t)R_TOTAL * H];

// ---------------------------------------------------------------------------
// Kernel 1: vm = X @ W^T     X:[32768,1024] (x flattened), W:[128,1024]
// Classic 128x128 block sgemm, BK=16, 256 threads, 8x8 per-thread tile.
// (At the scalar FFMA roofline — tensor-core rewrite is the next step.)
// ---------------------------------------------------------------------------
__global__ __launch_bounds__(256) void gemm_vm(const float* __restrict__ X,
                                               const float* __restrict__ W) {
    __shared__ float As[16][129];
    __shared__ float Bs[16][132];

    const int tid  = threadIdx.x;
    const int row0 = blockIdx.x * 128;
    const int tx   = tid & 15;      // 0..15 -> 8 output cols each
    const int ty   = tid >> 4;      // 0..15 -> 8 output rows each

    const int lk = (tid & 3) * 4;   // k offset within 16-wide K tile
    const int lr = tid >> 2;        // 0..63 row/head within tile half

    float acc[8][8];
    #pragma unroll
    for (int j = 0; j < 8; ++j)
        #pragma unroll
        for (int i = 0; i < 8; ++i) acc[j][i] = 0.f;

    for (int k0 = 0; k0 < NE; k0 += 16) {
        #pragma unroll
        for (int rr = 0; rr < 128; rr += 64) {
            float4 a = *reinterpret_cast<const float4*>(
                &X[(size_t)(row0 + lr + rr) * NE + k0 + lk]);
            As[lk + 0][lr + rr] = a.x;
            As[lk + 1][lr + rr] = a.y;
            As[lk + 2][lr + rr] = a.z;
            As[lk + 3][lr + rr] = a.w;
        }
        #pragma unroll
        for (int hh = 0; hh < 128; hh += 64) {
            float4 b = *reinterpret_cast<const float4*>(
                &W[(size_t)(lr + hh) * NE + k0 + lk]);
            Bs[lk + 0][lr + hh] = b.x;
            Bs[lk + 1][lr + hh] = b.y;
            Bs[lk + 2][lr + hh] = b.z;
            Bs[lk + 3][lr + hh] = b.w;
        }
        __syncthreads();

        #pragma unroll
        for (int k = 0; k < 16; ++k) {
            float a[8], b[8];
            #pragma unroll
            for (int j = 0; j < 8; ++j) a[j] = As[k][ty * 8 + j];
            #pragma unroll
            for (int i = 0; i < 8; ++i) b[i] = Bs[k][tx * 8 + i];
            #pragma unroll
            for (int j = 0; j < 8; ++j)
                #pragma unroll
                for (int i = 0; i < 8; ++i)
                    acc[j][i] = fmaf(a[j], b[i], acc[j][i]);
        }
        __syncthreads();
    }

    #pragma unroll
    for (int j = 0; j < 8; ++j) {
        float* dst = &g_vm[(size_t)(row0 + ty * 8 + j) * H + tx * 8];
        #pragma unroll
        for (int i = 0; i < 8; ++i) dst[i] = acc[j][i];
    }
}

// ---------------------------------------------------------------------------
// Kernel 2: fused softmax head, register-resident E (no smem E tile).
//   out[b][k] = sum_h (v_h / Z_h) * exp(m_h * cov[h][k]) + bias[k]
// One CTA (128 thr) per b. Warp w owns h-rows [32w,32w+32); lane l owns
// columns 4l..4l+3. Per h: 1 LDG.128 of cov, 4 EX2, warp-shuffle Z-reduce,
// 1 fast-div, 4 FMA into register accumulators. Single barrier for the
// 4-warp partial combine (2KB smem).
// ---------------------------------------------------------------------------
__device__ __forceinline__ float ex2f(float x) {
    float r;
    asm("ex2.approx.ftz.f32 %0, %1;" : "=f"(r) : "f"(x));
    return r;
}

__global__ __launch_bounds__(128) void head_out(const float* __restrict__ cov,
                                                const float* __restrict__ bias,
                                                float* __restrict__ out) {
    __shared__ float part[4][128];

    const int b = blockIdx.x;
    const int t = threadIdx.x;
    const int w = t >> 5;
    const int l = t & 31;
    const int hbase = w * 32;

    // lane l caches v,m for h = hbase + l; broadcast per-iteration via shfl.
    float v_reg = g_vm[(size_t)(2 * b + 0) * H + hbase + l];
    float m_reg = g_vm[(size_t)(2 * b + 1) * H + hbase + l]
                  * 1.4426950408889634f;   // fold log2(e) once

    float a0 = 0.f, a1 = 0.f, a2 = 0.f, a3 = 0.f;

    #pragma unroll 4
    for (int i = 0; i < 32; ++i) {
        const int h = hbase + i;
        const float mh = __shfl_sync(0xffffffffu, m_reg, i);
        const float vh = __shfl_sync(0xffffffffu, v_reg, i);
        const float4 c = __ldg(reinterpret_cast<const float4*>(
                                   cov + (size_t)h * H) + l);
        const float e0 = ex2f(mh * c.x);
        const float e1 = ex2f(mh * c.y);
        const float e2 = ex2f(mh * c.z);
        const float e3 = ex2f(mh * c.w);
        float s = (e0 + e1) + (e2 + e3);
        s += __shfl_xor_sync(0xffffffffu, s, 16);
        s += __shfl_xor_sync(0xffffffffu, s, 8);
        s += __shfl_xor_sync(0xffffffffu, s, 4);
        s += __shfl_xor_sync(0xffffffffu, s, 2);
        s += __shfl_xor_sync(0xffffffffu, s, 1);
        const float wh = __fdividef(vh, s);
        a0 = fmaf(wh, e0, a0);
        a1 = fmaf(wh, e1, a1);
        a2 = fmaf(wh, e2, a2);
        a3 = fmaf(wh, e3, a3);
    }

    *reinterpret_cast<float4*>(&part[w][4 * l]) = make_float4(a0, a1, a2, a3);
    __syncthreads();

    const float r = ((part[0][t] + part[1][t]) + (part[2][t] + part[3][t]))
                    + __ldg(bias + t);
    out[(size_t)b * H + t] = r;
}

// ---------------------------------------------------------------------------
extern "C" void kernel_launch(void* const* d_in, const int* in_sizes, int n_in,
                              void* d_out, int out_size) {
    const float* x    = (const float*)d_in[0];  // [16384,2,1024]
    const float* W    = (const float*)d_in[1];  // [128,1024]
    const float* cov  = (const float*)d_in[2];  // [128,128]
    const float* bias = (const float*)d_in[3];  // [128]
    float*       out  = (float*)d_out;          // [16384,128]

    gemm_vm<<<R_TOTAL / 128, 256>>>(x, W);
    head_out<<<16384, 128>>>(cov, bias, out);
}

// round 4
// speedup vs baseline: 2.8299x; 1.8581x over previous
#include <cuda_runtime.h>
#include <cuda_bf16.h>
#include <cstdint>

#define R_TOTAL 32768   // 16384 b * 2 (values,mask)
#define NE      1024
#define H       128

// Scratch: vm[2b+0]=values row, vm[2b+1]=mask row.
__device__ float g_vm[(size_t)R_TOTAL * H];

// W pre-split into bf16 hi/lo, packed in m16n8k16 B-fragment order:
//   [kstep(64)][natom(16)][lane(32)][reg(2)]  (b32 each = 2 bf16 along k)
__device__ uint32_t g_Bh[64 * 16 * 32 * 2];
__device__ uint32_t g_Bl[64 * 16 * 32 * 2];

// ---------------------------------------------------------------------------
// Kernel 0: split W -> bf16 hi/lo in B-fragment layout.
//   element (h=n, k): lane = 4*(h&7) + ((k&7)>>1), reg = (k>>3)&1,
//   low half of b32 = even-k element.
// ---------------------------------------------------------------------------
__global__ void prep_w(const float* __restrict__ W) {
    int idx = blockIdx.x * 256 + threadIdx.x;   // pair index over [h][kp]
    if (idx >= H * (NE / 2)) return;
    int h  = idx >> 9;          // 0..127
    int kp = idx & 511;         // k/2
    int k  = kp * 2;

    float w0 = W[(size_t)h * NE + k];
    float w1 = W[(size_t)h * NE + k + 1];
    uint32_t b0 = __float_as_uint(w0), b1 = __float_as_uint(w1);
    uint32_t hi;
    asm("prmt.b32 %0, %1, %2, 0x7632;" : "=r"(hi) : "r"(b0), "r"(b1));
    float l0 = w0 - __uint_as_float(b0 & 0xFFFF0000u);
    float l1 = w1 - __uint_as_float(b1 & 0xFFFF0000u);
    uint32_t lo;
    asm("cvt.rn.bf16x2.f32 %0, %1, %2;" : "=r"(lo) : "f"(l1), "f"(l0));

    int kstep = kp >> 3;              // k>>4
    int natom = h >> 3;
    int lane  = 4 * (h & 7) + (kp & 3);
    int reg   = (kp >> 2) & 1;        // (k>>3)&1
    int out   = ((kstep * 16 + natom) * 32 + lane) * 2 + reg;
    g_Bh[out] = hi;
    g_Bl[out] = lo;
}

// ---------------------------------------------------------------------------
// Kernel 1: vm = X @ W^T via mma.sync bf16 3-term split, fp32 accum.
// 256 CTAs x 256 thr (8 warps). M-tile 128, N=128, K-chunk 32 (2 ksteps).
// Warp (wm=wid&3, wn=wid>>2): rows wm*32..+31 (m-atoms 2wm,2wm+1),
// cols wn*64..+63 (n-atoms wn*8..+7).
// SMEM: A hi/lo in A-fragment layout [(s*8+a)*512 + lane*16 + reg*4],
//       B hi/lo straight copy of prepped fragment layout.
// ---------------------------------------------------------------------------
__device__ __forceinline__ void mma_bf16(float* d, const uint32_t* a,
                                         const uint32_t* b) {
    asm volatile(
        "mma.sync.aligned.m16n8k16.row.col.f32.bf16.bf16.f32 "
        "{%0,%1,%2,%3}, {%4,%5,%6,%7}, {%8,%9}, {%0,%1,%2,%3};"
        : "+f"(d[0]), "+f"(d[1]), "+f"(d[2]), "+f"(d[3])
        : "r"(a[0]), "r"(a[1]), "r"(a[2]), "r"(a[3]), "r"(b[0]), "r"(b[1]));
}

__global__ __launch_bounds__(256, 2) void gemm_vm_tc(const float* __restrict__ X) {
    __shared__ uint32_t sAh[2 * 8 * 32 * 4];   // 8KB: [s*8+a][lane][4]
    __shared__ uint32_t sAl[2 * 8 * 32 * 4];   // 8KB
    __shared__ uint32_t sBh[2 * 16 * 32 * 2];  // 8KB: [s][natom][lane][2]
    __shared__ uint32_t sBl[2 * 16 * 32 * 2];  // 8KB

    const int tid  = threadIdx.x;
    const int wid  = tid >> 5;
    const int lane = tid & 31;
    const int row0 = blockIdx.x * 128;
    const int wm   = wid & 3;
    const int wn   = wid >> 2;

    float acc[2][8][4];
    #pragma unroll
    for (int i = 0; i < 2; ++i)
        #pragma unroll
        for (int j = 0; j < 8; ++j)
            #pragma unroll
            for (int q = 0; q < 4; ++q) acc[i][j][q] = 0.f;

    for (int c = 0; c < NE / 32; ++c) {          // 32 chunks of K=32
        // ---- stage A chunk: load f32, split, store in fragment layout ----
        #pragma unroll
        for (int j = 0; j < 4; ++j) {
            int idx = tid + j * 256;             // 0..1023 float4s
            int r   = idx >> 3;                  // row 0..127
            int c4  = idx & 7;                   // float4 within 32-k chunk
            float4 v = __ldg(reinterpret_cast<const float4*>(
                                 X + (size_t)(row0 + r) * NE) + c * 8 + c4);
            uint32_t x0 = __float_as_uint(v.x), x1 = __float_as_uint(v.y);
            uint32_t x2 = __float_as_uint(v.z), x3 = __float_as_uint(v.w);
            uint32_t hi01, hi23;
            asm("prmt.b32 %0, %1, %2, 0x7632;" : "=r"(hi01) : "r"(x0), "r"(x1));
            asm("prmt.b32 %0, %1, %2, 0x7632;" : "=r"(hi23) : "r"(x2), "r"(x3));
            float l0 = v.x - __uint_as_float(x0 & 0xFFFF0000u);
            float l1 = v.y - __uint_as_float(x1 & 0xFFFF0000u);
            float l2 = v.z - __uint_as_float(x2 & 0xFFFF0000u);
            float l3 = v.w - __uint_as_float(x3 & 0xFFFF0000u);
            uint32_t lo01, lo23;
            asm("cvt.rn.bf16x2.f32 %0, %1, %2;" : "=r"(lo01) : "f"(l1), "f"(l0));
            asm("cvt.rn.bf16x2.f32 %0, %1, %2;" : "=r"(lo23) : "f"(l3), "f"(l2));
            // b32-pair coords: (r, cc0) and (r, cc0+1), cc0 = 2*c4 (0..15)
            int rr = r & 15, a = r >> 4;
            #pragma unroll
            for (int p = 0; p < 2; ++p) {
                int cc = 2 * c4 + p;
                int s  = cc >> 3;
                int c8 = cc & 7;
                int ln = (rr & 7) * 4 + (c8 & 3);
                int rg = (rr >> 3) + 2 * (c8 >> 2);
                int e  = ((s * 8 + a) * 32 + ln) * 4 + rg;
                sAh[e] = p ? hi23 : hi01;
                sAl[e] = p ? lo23 : lo01;
            }
        }
        // ---- stage B chunk: straight copy, 2 ksteps x (hi+lo) ----
        {
            const uint4* gh = reinterpret_cast<const uint4*>(g_Bh + c * 2048);
            const uint4* gl = reinterpret_cast<const uint4*>(g_Bl + c * 2048);
            uint4* dh = reinterpret_cast<uint4*>(sBh);
            uint4* dl = reinterpret_cast<uint4*>(sBl);
            dh[tid]       = gh[tid];
            dh[tid + 256] = gh[tid + 256];
            dl[tid]       = gl[tid];
            dl[tid + 256] = gl[tid + 256];
        }
        __syncthreads();

        // ---- MMA: 2 ksteps x 2 m-atoms x 8 n-atoms x 3 terms ----
        #pragma unroll
        for (int s = 0; s < 2; ++s) {
            uint32_t ah[2][4], al[2][4];
            #pragma unroll
            for (int i = 0; i < 2; ++i) {
                const uint32_t* pa = &sAh[((s * 8 + wm * 2 + i) * 32 + lane) * 4];
                ah[i][0] = pa[0]; ah[i][1] = pa[1]; ah[i][2] = pa[2]; ah[i][3] = pa[3];
                const uint32_t* pl = &sAl[((s * 8 + wm * 2 + i) * 32 + lane) * 4];
                al[i][0] = pl[0]; al[i][1] = pl[1]; al[i][2] = pl[2]; al[i][3] = pl[3];
            }
            #pragma unroll
            for (int jh = 0; jh < 2; ++jh) {
                uint32_t bh[4][2], bl[4][2];
                #pragma unroll
                for (int jj = 0; jj < 4; ++jj) {
                    int na = wn * 8 + jh * 4 + jj;
                    const uint32_t* pb = &sBh[(s * 16 + na) * 64 + lane * 2];
                    bh[jj][0] = pb[0]; bh[jj][1] = pb[1];
                    const uint32_t* ql = &sBl[(s * 16 + na) * 64 + lane * 2];
                    bl[jj][0] = ql[0]; bl[jj][1] = ql[1];
                }
                #pragma unroll
                for (int i = 0; i < 2; ++i)
                    #pragma unroll
                    for (int jj = 0; jj < 4; ++jj) {
                        float* d = acc[i][jh * 4 + jj];
                        mma_bf16(d, ah[i], bh[jj]);
                        mma_bf16(d, ah[i], bl[jj]);
                        mma_bf16(d, al[i], bh[jj]);
                    }
            }
        }
        __syncthreads();
    }

    // ---- epilogue: D fragments -> g_vm ----
    #pragma unroll
    for (int i = 0; i < 2; ++i) {
        int grow = row0 + wm * 32 + i * 16 + (lane >> 2);
        #pragma unroll
        for (int j = 0; j < 8; ++j) {
            int gcol = wn * 64 + j * 8 + 2 * (lane & 3);
            float2* p0 = reinterpret_cast<float2*>(&g_vm[(size_t)grow * H + gcol]);
            float2* p1 = reinterpret_cast<float2*>(&g_vm[(size_t)(grow + 8) * H + gcol]);
            *p0 = make_float2(acc[i][j][0], acc[i][j][1]);
            *p1 = make_float2(acc[i][j][2], acc[i][j][3]);
        }
    }
}

// ---------------------------------------------------------------------------
// Kernel 2: fused softmax head (register-resident E) — unchanged from R2.
// ---------------------------------------------------------------------------
__device__ __forceinline__ float ex2f(float x) {
    float r;
    asm("ex2.approx.ftz.f32 %0, %1;" : "=f"(r) : "f"(x));
    return r;
}

__global__ __launch_bounds__(128) void head_out(const float* __restrict__ cov,
                                                const float* __restrict__ bias,
                                                float* __restrict__ out) {
    __shared__ float part[4][128];

    const int b = blockIdx.x;
    const int t = threadIdx.x;
    const int w = t >> 5;
    const int l = t & 31;
    const int hbase = w * 32;

    float v_reg = g_vm[(size_t)(2 * b + 0) * H + hbase + l];
    float m_reg = g_vm[(size_t)(2 * b + 1) * H + hbase + l]
                  * 1.4426950408889634f;

    float a0 = 0.f, a1 = 0.f, a2 = 0.f, a3 = 0.f;

    #pragma unroll 4
    for (int i = 0; i < 32; ++i) {
        const int h = hbase + i;
        const float mh = __shfl_sync(0xffffffffu, m_reg, i);
        const float vh = __shfl_sync(0xffffffffu, v_reg, i);
        const float4 c = __ldg(reinterpret_cast<const float4*>(
                                   cov + (size_t)h * H) + l);
        const float e0 = ex2f(mh * c.x);
        const float e1 = ex2f(mh * c.y);
        const float e2 = ex2f(mh * c.z);
        const float e3 = ex2f(mh * c.w);
        float s = (e0 + e1) + (e2 + e3);
        s += __shfl_xor_sync(0xffffffffu, s, 16);
        s += __shfl_xor_sync(0xffffffffu, s, 8);
        s += __shfl_xor_sync(0xffffffffu, s, 4);
        s += __shfl_xor_sync(0xffffffffu, s, 2);
        s += __shfl_xor_sync(0xffffffffu, s, 1);
        const float wh = __fdividef(vh, s);
        a0 = fmaf(wh, e0, a0);
        a1 = fmaf(wh, e1, a1);
        a2 = fmaf(wh, e2, a2);
        a3 = fmaf(wh, e3, a3);
    }

    *reinterpret_cast<float4*>(&part[w][4 * l]) = make_float4(a0, a1, a2, a3);
    __syncthreads();

    const float r = ((part[0][t] + part[1][t]) + (part[2][t] + part[3][t]))
                    + __ldg(bias + t);
    out[(size_t)b * H + t] = r;
}

// ---------------------------------------------------------------------------
extern "C" void kernel_launch(void* const* d_in, const int* in_sizes, int n_in,
                              void* d_out, int out_size) {
    const float* x    = (const float*)d_in[0];  // [16384,2,1024]
    const float* W    = (const float*)d_in[1];  // [128,1024]
    const float* cov  = (const float*)d_in[2];  // [128,128]
    const float* bias = (const float*)d_in[3];  // [128]
    float*       out  = (float*)d_out;          // [16384,128]

    prep_w<<<(H * NE / 2 + 255) / 256, 256>>>(W);
    gemm_vm_tc<<<R_TOTAL / 128, 256>>>(x);
    head_out<<<16384, 128>>>(cov, bias, out);
}

// round 7
// speedup vs baseline: 2.9379x; 1.0382x over previous
#include <cuda_runtime.h>
#include <cuda_bf16.h>
#include <cstdint>

#define R_TOTAL 32768   // 16384 b * 2 (values,mask)
#define NE      1024
#define H       128
#define NCH     32      // K-chunks of 32

// Scratch: vm[2b+0]=values row, vm[2b+1]=mask row.
__device__ float g_vm[(size_t)R_TOTAL * H];

// W pre-split into bf16 hi/lo, packed in m16n8k16 B-fragment order:
//   [kstep(64)][natom(16)][lane(32)][reg(2)]  (b32 each = 2 bf16 along k)
__device__ uint32_t g_Bh[64 * 16 * 32 * 2];
__device__ uint32_t g_Bl[64 * 16 * 32 * 2];

// ---------------------------------------------------------------------------
// Kernel 0: split W -> bf16 hi/lo in B-fragment layout.
// ---------------------------------------------------------------------------
__global__ void prep_w(const float* __restrict__ W) {
    int idx = blockIdx.x * 256 + threadIdx.x;   // pair index over [h][kp]
    if (idx >= H * (NE / 2)) return;
    int h  = idx >> 9;          // 0..127
    int kp = idx & 511;         // k/2
    int k  = kp * 2;

    float w0 = W[(size_t)h * NE + k];
    float w1 = W[(size_t)h * NE + k + 1];
    uint32_t b0 = __float_as_uint(w0), b1 = __float_as_uint(w1);
    uint32_t hi;
    asm("prmt.b32 %0, %1, %2, 0x7632;" : "=r"(hi) : "r"(b0), "r"(b1));
    float l0 = w0 - __uint_as_float(b0 & 0xFFFF0000u);
    float l1 = w1 - __uint_as_float(b1 & 0xFFFF0000u);
    uint32_t lo;
    asm("cvt.rn.bf16x2.f32 %0, %1, %2;" : "=r"(lo) : "f"(l1), "f"(l0));

    int kstep = kp >> 3;
    int natom = h >> 3;
    int lane  = 4 * (h & 7) + (kp & 3);
    int reg   = (kp >> 2) & 1;
    int out   = ((kstep * 16 + natom) * 32 + lane) * 2 + reg;
    g_Bh[out] = hi;
    g_Bl[out] = lo;
}

// ---------------------------------------------------------------------------
// Kernel 1: vm = X @ W^T via mma.sync bf16 3-term split, fp32 accum.
// Pipelined, race-free: A prefetch->regs, B via cp.async double buffer,
// cp.async issued ONLY after the barrier that retires its buffer's readers.
// Static SMEM 48KB: sA (hi|lo, single buf) + sB[2] (hi|lo).
// ---------------------------------------------------------------------------
__device__ __forceinline__ void mma_bf16(float* d, const uint32_t* a,
                                         const uint32_t* b) {
    asm volatile(
        "mma.sync.aligned.m16n8k16.row.col.f32.bf16.bf16.f32 "
        "{%0,%1,%2,%3}, {%4,%5,%6,%7}, {%8,%9}, {%0,%1,%2,%3};"
        : "+f"(d[0]), "+f"(d[1]), "+f"(d[2]), "+f"(d[3])
        : "r"(a[0]), "r"(a[1]), "r"(a[2]), "r"(a[3]), "r"(b[0]), "r"(b[1]));
}

__device__ __forceinline__ uint32_t smem_u32(const void* p) {
    uint32_t a;
    asm("{ .reg .u64 t; cvta.to.shared.u64 t, %1; cvt.u32.u64 %0, t; }"
        : "=r"(a) : "l"(p));
    return a;
}
__device__ __forceinline__ void cp_async16(uint32_t s, const void* g) {
    asm volatile("cp.async.cg.shared.global [%0], [%1], 16;"
                 :: "r"(s), "l"(g) : "memory");
}

__global__ __launch_bounds__(256, 2) void gemm_vm_tc(const float* __restrict__ X) {
    __shared__ uint32_t sA[4096];       // 16KB: hi[2048] | lo[2048]
    __shared__ uint32_t sB[2][4096];    // 32KB: per buf hi[2048] | lo[2048]
    uint32_t* sAh = sA;
    uint32_t* sAl = sA + 2048;

    const int tid  = threadIdx.x;
    const int wid  = tid >> 5;
    const int lane = tid & 31;
    const int row0 = blockIdx.x * 128;
    const int wm   = wid & 3;
    const int wn   = wid >> 2;

    // This thread's fixed A-load coords (4 float4s per chunk)
    const int ar[4] = { (tid + 0)   >> 3, (tid + 256) >> 3,
                        (tid + 512) >> 3, (tid + 768) >> 3 };
    const int ac4   = tid & 7;

    float acc[2][8][4];
    #pragma unroll
    for (int i = 0; i < 2; ++i)
        #pragma unroll
        for (int j = 0; j < 8; ++j)
            #pragma unroll
            for (int q = 0; q < 4; ++q) acc[i][j][q] = 0.f;

    // ---- prologue: A chunk 0 -> regs; B chunk 0 -> cp.async into sB[0] ----
    float4 pref[4];
    #pragma unroll
    for (int j = 0; j < 4; ++j)
        pref[j] = __ldg(reinterpret_cast<const float4*>(
                            X + (size_t)(row0 + ar[j]) * NE) + ac4);
    {
        const char* gh = reinterpret_cast<const char*>(g_Bh);
        const char* gl = reinterpret_cast<const char*>(g_Bl);
        uint32_t db = smem_u32(sB[0]);
        int e = tid * 16;
        cp_async16(db + e,             gh + e);
        cp_async16(db + 8192 + e,      gl + e);
        cp_async16(db + e + 4096,      gh + e + 4096);
        cp_async16(db + 8192 + e + 4096, gl + e + 4096);
        asm volatile("cp.async.commit_group;" ::: "memory");
    }

    for (int c = 0; c < NCH; ++c) {
        const int cur = c & 1;

        // barrier (1): all iter c-1 MMA reads of sA and sB[cur^1] retired.
        __syncthreads();

        // ---- convert prefetched A regs -> fragment-layout smem (sA) ----
        #pragma unroll
        for (int j = 0; j < 4; ++j) {
            float4 v = pref[j];
            uint32_t x0 = __float_as_uint(v.x), x1 = __float_as_uint(v.y);
            uint32_t x2 = __float_as_uint(v.z), x3 = __float_as_uint(v.w);
            uint32_t hi01, hi23;
            asm("prmt.b32 %0, %1, %2, 0x7632;" : "=r"(hi01) : "r"(x0), "r"(x1));
            asm("prmt.b32 %0, %1, %2, 0x7632;" : "=r"(hi23) : "r"(x2), "r"(x3));
            float l0 = v.x - __uint_as_float(x0 & 0xFFFF0000u);
            float l1 = v.y - __uint_as_float(x1 & 0xFFFF0000u);
            float l2 = v.z - __uint_as_float(x2 & 0xFFFF0000u);
            float l3 = v.w - __uint_as_float(x3 & 0xFFFF0000u);
            uint32_t lo01, lo23;
            asm("cvt.rn.bf16x2.f32 %0, %1, %2;" : "=r"(lo01) : "f"(l1), "f"(l0));
            asm("cvt.rn.bf16x2.f32 %0, %1, %2;" : "=r"(lo23) : "f"(l3), "f"(l2));
            int rr = ar[j] & 15, a = ar[j] >> 4;
            #pragma unroll
            for (int p = 0; p < 2; ++p) {
                int cc = 2 * ac4 + p;
                int s  = cc >> 3;
                int c8 = cc & 7;
                int ln = (rr & 7) * 4 + (c8 & 3);
                int rg = (rr >> 3) + 2 * (c8 >> 2);
                int e  = ((s * 8 + a) * 32 + ln) * 4 + rg;
                sAh[e] = p ? hi23 : hi01;
                sAl[e] = p ? lo23 : lo01;
            }
        }

        // ---- prefetch next chunk (post-barrier: destination buffer free) ----
        if (c + 1 < NCH) {
            const char* gh = reinterpret_cast<const char*>(g_Bh + (c + 1) * 2048);
            const char* gl = reinterpret_cast<const char*>(g_Bl + (c + 1) * 2048);
            uint32_t db = smem_u32(sB[cur ^ 1]);
            int e = tid * 16;
            cp_async16(db + e,               gh + e);
            cp_async16(db + 8192 + e,        gl + e);
            cp_async16(db + e + 4096,        gh + e + 4096);
            cp_async16(db + 8192 + e + 4096, gl + e + 4096);
            asm volatile("cp.async.commit_group;" ::: "memory");
            const float* Xn = X + (c + 1) * 32;
            #pragma unroll
            for (int j = 0; j < 4; ++j)
                pref[j] = __ldg(reinterpret_cast<const float4*>(
                                    Xn + (size_t)(row0 + ar[j]) * NE) + ac4);
            asm volatile("cp.async.wait_group 1;" ::: "memory");  // chunk c done
        } else {
            asm volatile("cp.async.wait_group 0;" ::: "memory");
        }

        // barrier (2): sA converted + sB[cur] landed, visible to all.
        __syncthreads();

        uint32_t* Bh = sB[cur];
        uint32_t* Bl = sB[cur] + 2048;

        // ---- MMA: 2 ksteps x 2 m-atoms x 8 n-atoms x 3 terms ----
        #pragma unroll
        for (int s = 0; s < 2; ++s) {
            uint32_t ah[2][4], al[2][4];
            #pragma unroll
            for (int i = 0; i < 2; ++i) {
                const uint32_t* pa = &sAh[((s * 8 + wm * 2 + i) * 32 + lane) * 4];
                ah[i][0] = pa[0]; ah[i][1] = pa[1]; ah[i][2] = pa[2]; ah[i][3] = pa[3];
                const uint32_t* pl = &sAl[((s * 8 + wm * 2 + i) * 32 + lane) * 4];
                al[i][0] = pl[0]; al[i][1] = pl[1]; al[i][2] = pl[2]; al[i][3] = pl[3];
            }
            #pragma unroll
            for (int jh = 0; jh < 2; ++jh) {
                uint32_t bh[4][2], bl[4][2];
                #pragma unroll
                for (int jj = 0; jj < 4; ++jj) {
                    int na = wn * 8 + jh * 4 + jj;
                    const uint32_t* pb = &Bh[(s * 16 + na) * 64 + lane * 2];
                    bh[jj][0] = pb[0]; bh[jj][1] = pb[1];
                    const uint32_t* ql = &Bl[(s * 16 + na) * 64 + lane * 2];
                    bl[jj][0] = ql[0]; bl[jj][1] = ql[1];
                }
                #pragma unroll
                for (int i = 0; i < 2; ++i)
                    #pragma unroll
                    for (int jj = 0; jj < 4; ++jj) {
                        float* d = acc[i][jh * 4 + jj];
                        mma_bf16(d, ah[i], bh[jj]);
                        mma_bf16(d, ah[i], bl[jj]);
                        mma_bf16(d, al[i], bh[jj]);
                    }
            }
        }
    }

    // ---- epilogue: D fragments -> g_vm ----
    #pragma unroll
    for (int i = 0; i < 2; ++i) {
        int grow = row0 + wm * 32 + i * 16 + (lane >> 2);
        #pragma unroll
        for (int j = 0; j < 8; ++j) {
            int gcol = wn * 64 + j * 8 + 2 * (lane & 3);
            float2* p0 = reinterpret_cast<float2*>(&g_vm[(size_t)grow * H + gcol]);
            float2* p1 = reinterpret_cast<float2*>(&g_vm[(size_t)(grow + 8) * H + gcol]);
            *p0 = make_float2(acc[i][j][0], acc[i][j][1]);
            *p1 = make_float2(acc[i][j][2], acc[i][j][3]);
        }
    }
}

// ---------------------------------------------------------------------------
// Kernel 2: fused softmax head (register-resident E) — unchanged.
// ---------------------------------------------------------------------------
__device__ __forceinline__ float ex2f(float x) {
    float r;
    asm("ex2.approx.ftz.f32 %0, %1;" : "=f"(r) : "f"(x));
    return r;
}

__global__ __launch_bounds__(128) void head_out(const float* __restrict__ cov,
                                                const float* __restrict__ bias,
                                                float* __restrict__ out) {
    __shared__ float part[4][128];

    const int b = blockIdx.x;
    const int t = threadIdx.x;
    const int w = t >> 5;
    const int l = t & 31;
    const int hbase = w * 32;

    float v_reg = g_vm[(size_t)(2 * b + 0) * H + hbase + l];
    float m_reg = g_vm[(size_t)(2 * b + 1) * H + hbase + l]
                  * 1.4426950408889634f;

    float a0 = 0.f, a1 = 0.f, a2 = 0.f, a3 = 0.f;

    #pragma unroll 4
    for (int i = 0; i < 32; ++i) {
        const int h = hbase + i;
        const float mh = __shfl_sync(0xffffffffu, m_reg, i);
        const float vh = __shfl_sync(0xffffffffu, v_reg, i);
        const float4 c = __ldg(reinterpret_cast<const float4*>(
                                   cov + (size_t)h * H) + l);
        const float e0 = ex2f(mh * c.x);
        const float e1 = ex2f(mh * c.y);
        const float e2 = ex2f(mh * c.z);
        const float e3 = ex2f(mh * c.w);
        float s = (e0 + e1) + (e2 + e3);
        s += __shfl_xor_sync(0xffffffffu, s, 16);
        s += __shfl_xor_sync(0xffffffffu, s, 8);
        s += __shfl_xor_sync(0xffffffffu, s, 4);
        s += __shfl_xor_sync(0xffffffffu, s, 2);
        s += __shfl_xor_sync(0xffffffffu, s, 1);
        const float wh = __fdividef(vh, s);
        a0 = fmaf(wh, e0, a0);
        a1 = fmaf(wh, e1, a1);
        a2 = fmaf(wh, e2, a2);
        a3 = fmaf(wh, e3, a3);
    }

    *reinterpret_cast<float4*>(&part[w][4 * l]) = make_float4(a0, a1, a2, a3);
    __syncthreads();

    const float r = ((part[0][t] + part[1][t]) + (part[2][t] + part[3][t]))
                    + __ldg(bias + t);
    out[(size_t)b * H + t] = r;
}

// ---------------------------------------------------------------------------
extern "C" void kernel_launch(void* const* d_in, const int* in_sizes, int n_in,
                              void* d_out, int out_size) {
    const float* x    = (const float*)d_in[0];  // [16384,2,1024]
    const float* W    = (const float*)d_in[1];  // [128,1024]
    const float* cov  = (const float*)d_in[2];  // [128,128]
    const float* bias = (const float*)d_in[3];  // [128]
    float*       out  = (float*)d_out;          // [16384,128]

    prep_w<<<(H * NE / 2 + 255) / 256, 256>>>(W);
    gemm_vm_tc<<<R_TOTAL / 128, 256>>>(x);
    head_out<<<16384, 128>>>(cov, bias, out);
}